// round 12
// baseline (speedup 1.0000x reference)
#include <cuda_runtime.h>
#include <cuda_fp16.h>
#include <math.h>
#include <stdint.h>

#define BATCH 4
#define NTOK 1024
#define DIM 1024
#define NHEAD 8
#define DHEAD 128
#define ROWS (BATCH*NTOK)
#define ZB (BATCH*NHEAD)
#define ATTN_SCALE 0.08838834764831845f
#define LN_EPS 1e-5f

/* ------------------- device scratch ------------------- */
__device__ __half g_xn16[ROWS*DIM];
__device__ __half g_cn16[ROWS*DIM];
__device__ __half g_rn16[ROWS*DIM];
__device__ __half g_cond16[ROWS*DIM];
__device__ __half g_refv16[ROWS*DIM];
__device__ __half g_outpre16[ROWS*DIM];
__device__ __half g_attn16[(size_t)ZB*NTOK*NTOK];
__device__ __half g_ctx16[(size_t)ZB*NTOK*NTOK];
__device__ __half g_sim16[(size_t)ZB*NTOK*NTOK];
__device__ __half g_Wk16[3*DIM*DIM];
__device__ __half g_Wv16[2*DIM*DIM];
__device__ __half g_Wo16[DIM*DIM];
__device__ float  g_rinv[ZB*NTOK];
__device__ float  g_cinv[ZB*NTOK];
__device__ float  g_cpart[8*ZB*NTOK];

/* ------------------- asm helpers ------------------- */
__device__ __forceinline__ uint32_t smaddr(const void* p) {
    return (uint32_t)__cvta_generic_to_shared(p);
}
__device__ __forceinline__ void ldsm4(uint32_t& r0, uint32_t& r1, uint32_t& r2, uint32_t& r3, uint32_t a) {
    asm volatile("ldmatrix.sync.aligned.m8n8.x4.shared.b16 {%0,%1,%2,%3},[%4];"
        : "=r"(r0), "=r"(r1), "=r"(r2), "=r"(r3) : "r"(a));
}
__device__ __forceinline__ void ldsm4t(uint32_t& r0, uint32_t& r1, uint32_t& r2, uint32_t& r3, uint32_t a) {
    asm volatile("ldmatrix.sync.aligned.m8n8.x4.trans.shared.b16 {%0,%1,%2,%3},[%4];"
        : "=r"(r0), "=r"(r1), "=r"(r2), "=r"(r3) : "r"(a));
}
__device__ __forceinline__ void mma_f16(float c[4], const uint32_t a[4], const uint32_t b[2]) {
    asm volatile(
        "mma.sync.aligned.m16n8k16.row.col.f32.f16.f16.f32 "
        "{%0,%1,%2,%3},{%4,%5,%6,%7},{%8,%9},{%0,%1,%2,%3};"
        : "+f"(c[0]), "+f"(c[1]), "+f"(c[2]), "+f"(c[3])
        : "r"(a[0]), "r"(a[1]), "r"(a[2]), "r"(a[3]), "r"(b[0]), "r"(b[1]));
}
__device__ __forceinline__ void cp_async16(void* smem_dst, const void* gsrc) {
    uint32_t d = smaddr(smem_dst);
    asm volatile("cp.async.cg.shared.global [%0], [%1], 16;" :: "r"(d), "l"(gsrc));
}
#define CP_COMMIT() asm volatile("cp.async.commit_group;")
#define CP_WAIT(n)  asm volatile("cp.async.wait_group %0;" :: "n"(n))

/* ------------------------------------------------------------------ */
/* f16 mma.sync GEMM: CTA 256x128, BK=32, 3-stage cp.async, 8 warps,   */
/* warp tile 64x64 (4 MMA per LDSM).                                   */
/* AL: 0 = A [m][k], 1 = A [k][m]. BL: 0 = B [k][n], 1 = B [n][k].     */
/* EPI: 0 f32, 2 f16, 3 f32+bias, 4 f16*scale                          */
/* ------------------------------------------------------------------ */
template<int AL, int BL, int NSEG, int EPI>
__global__ __launch_bounds__(256, 1)
void k_hgemm(const __half* __restrict__ A0, const __half* __restrict__ A1,
             const __half* __restrict__ A2, int lda,
             const __half* __restrict__ B, int ldb,
             float* __restrict__ Cf, __half* __restrict__ Ch, int ldc, int Ktot,
             const float* __restrict__ bias,
             size_t sAb, size_t sAh, size_t sBb, size_t sBh,
             size_t sCb, size_t sCh)
{
    constexpr int PA = AL ? 264 : 40;              /* pitch in halves */
    constexpr int PB = BL ? 40 : 136;
    constexpr int ASZ = AL ? 32*264 : 256*40;
    constexpr int BSZ = BL ? 128*40 : 32*136;
    constexpr int STG = 3;

    extern __shared__ __half sm16[];
    __half* Asm = sm16;
    __half* Bsm = sm16 + STG*ASZ;

    const int z = blockIdx.z, zb = z >> 3, zh = z & 7;
    const __half* Az = A0 + zb*sAb + zh*sAh;
    const __half* Bz = B  + zb*sBb + zh*sBh;

    const int tid = threadIdx.x;
    const int bm = blockIdx.y, bn = blockIdx.x;
    const int NIT = Ktot >> 5;

    const int wid = tid >> 5, lane = tid & 31;
    const int gid = lane >> 2, tig = lane & 3;
    const int wm = (wid >> 1) * 64, wn = (wid & 1) * 64;

    float acc[4][8][4];
    #pragma unroll
    for (int i = 0; i < 4; i++)
        #pragma unroll
        for (int j = 0; j < 8; j++)
            #pragma unroll
            for (int k = 0; k < 4; k++) acc[i][j][k] = 0.f;

    auto load_stage = [&](int st, int it) {
        const int k0 = it << 5;
        __half* as = Asm + st*ASZ;
        __half* bs = Bsm + st*BSZ;
        const __half* Ap = Az;
        int kc = k0;
        if (NSEG > 1) {
            int s = k0 >> 10;
            Ap = (s == 0) ? A0 : (s == 1) ? A1 : A2;
            kc = k0 & 1023;
        }
        #pragma unroll
        for (int j = 0; j < 4; j++) {
            int id = tid + j*256;
            if (AL == 0) {
                int r = id >> 2, c = (id & 3) * 8;
                cp_async16(as + r*PA + c, Ap + (size_t)(bm*256 + r)*lda + kc + c);
            } else {
                int r = id >> 5, c = (id & 31) * 8;
                cp_async16(as + r*PA + c, Az + (size_t)(k0 + r)*lda + bm*256 + c);
            }
        }
        #pragma unroll
        for (int j = 0; j < 2; j++) {
            int id = tid + j*256;
            if (BL == 0) {
                int r = id >> 4, c = (id & 15) * 8;
                cp_async16(bs + r*PB + c, Bz + (size_t)(k0 + r)*ldb + bn*128 + c);
            } else {
                int r = id >> 2, c = (id & 3) * 8;
                cp_async16(bs + r*PB + c, Bz + (size_t)(bn*128 + r)*ldb + k0 + c);
            }
        }
    };

    auto compute_stage = [&](int st) {
        const __half* as = Asm + st*ASZ;
        const __half* bs = Bsm + st*BSZ;
        const int g8 = lane >> 3, i8 = lane & 7;
        #pragma unroll
        for (int ks = 0; ks < 2; ks++) {
            uint32_t af[4][4];
            #pragma unroll
            for (int mt = 0; mt < 4; mt++) {
                if (AL == 0) {
                    uint32_t a = smaddr(as + (wm + mt*16 + (lane & 15))*PA + ks*16 + (lane >> 4)*8);
                    ldsm4(af[mt][0], af[mt][1], af[mt][2], af[mt][3], a);
                } else {
                    uint32_t a = smaddr(as + (ks*16 + (g8 >> 1)*8 + i8)*PA + wm + mt*16 + (g8 & 1)*8);
                    ldsm4t(af[mt][0], af[mt][1], af[mt][2], af[mt][3], a);
                }
            }
            uint32_t bf[8][2];
            #pragma unroll
            for (int p = 0; p < 4; p++) {
                uint32_t q0, q1, q2, q3;
                if (BL == 1) {
                    uint32_t a = smaddr(bs + (wn + p*16 + (g8 >> 1)*8 + i8)*PB + ks*16 + (g8 & 1)*8);
                    ldsm4(q0, q1, q2, q3, a);
                } else {
                    uint32_t a = smaddr(bs + (ks*16 + (g8 & 1)*8 + i8)*PB + wn + p*16 + (g8 >> 1)*8);
                    ldsm4t(q0, q1, q2, q3, a);
                }
                bf[2*p][0] = q0; bf[2*p][1] = q1;
                bf[2*p+1][0] = q2; bf[2*p+1][1] = q3;
            }
            #pragma unroll
            for (int mt = 0; mt < 4; mt++)
                #pragma unroll
                for (int nt = 0; nt < 8; nt++)
                    mma_f16(acc[mt][nt], af[mt], bf[nt]);
        }
    };

    load_stage(0, 0); CP_COMMIT();
    load_stage(1, 1); CP_COMMIT();
    int buf = 0;
    for (int it = 0; it < NIT; ++it) {
        CP_WAIT(1);
        __syncthreads();
        if (it + 2 < NIT) load_stage((buf + 2 >= STG) ? buf + 2 - STG : buf + 2, it + 2);
        CP_COMMIT();
        compute_stage(buf);
        buf = (buf + 1 >= STG) ? buf + 1 - STG : buf + 1;
    }

    /* epilogue */
    float* Cfz = (EPI == 0 || EPI == 3) ? Cf + zb*sCb + zh*sCh : nullptr;
    __half* Chz = (EPI == 2 || EPI == 4) ? Ch + zb*sCb + zh*sCh : nullptr;
    #pragma unroll
    for (int mt = 0; mt < 4; mt++) {
        #pragma unroll
        for (int nt = 0; nt < 8; nt++) {
            int r0  = bm*256 + wm + mt*16 + gid;
            int col = bn*128 + wn + nt*8 + 2*tig;
            float c0 = acc[mt][nt][0], c1 = acc[mt][nt][1];
            float c2 = acc[mt][nt][2], c3 = acc[mt][nt][3];
            if (EPI == 4) { c0 *= ATTN_SCALE; c1 *= ATTN_SCALE; c2 *= ATTN_SCALE; c3 *= ATTN_SCALE; }
            if (EPI == 3) {
                float2 bv = *(const float2*)(bias + col);
                c0 += bv.x; c1 += bv.y; c2 += bv.x; c3 += bv.y;
            }
            if (EPI == 2 || EPI == 4) {
                *(__half2*)&Chz[(size_t)r0*ldc + col]     = __floats2half2_rn(c0, c1);
                *(__half2*)&Chz[(size_t)(r0+8)*ldc + col] = __floats2half2_rn(c2, c3);
            } else {
                *(float2*)&Cfz[(size_t)r0*ldc + col]     = make_float2(c0, c1);
                *(float2*)&Cfz[(size_t)(r0+8)*ldc + col] = make_float2(c2, c3);
            }
        }
    }
}

/* ------------------- f32 -> f16 convert ------------------- */
__global__ __launch_bounds__(256)
void k_f2h(const float* __restrict__ s, __half* __restrict__ d, int n)
{
    int i = (blockIdx.x * 256 + threadIdx.x) * 4;
    if (i < n) {
        float4 v = *(const float4*)(s + i);
        *(__half2*)(d + i)     = __floats2half2_rn(v.x, v.y);
        *(__half2*)(d + i + 2) = __floats2half2_rn(v.z, v.w);
    }
}

/* ------------------- LayerNorm -> f16 ------------------- */
__global__ __launch_bounds__(256)
void k_layernorm(const float* __restrict__ x, const float* __restrict__ ci,
                 const float* __restrict__ ref,
                 const float* __restrict__ lw, const float* __restrict__ lb,
                 const float* __restrict__ cw, const float* __restrict__ cb)
{
    int row = blockIdx.x;
    int which = blockIdx.y;
    const float* src = (which == 0) ? x : (which == 1) ? ref : ci;
    const float* w   = (which == 2) ? cw : lw;
    const float* bb  = (which == 2) ? cb : lb;
    __half* dst      = (which == 0) ? g_xn16 : (which == 1) ? g_rn16 : g_cn16;

    const float* p = src + (size_t)row * DIM;
    int t = threadIdx.x;
    float4 v = *(const float4*)(p + t * 4);
    float s  = v.x + v.y + v.z + v.w;
    float s2 = v.x*v.x + v.y*v.y + v.z*v.z + v.w*v.w;
    for (int o = 16; o; o >>= 1) {
        s  += __shfl_xor_sync(0xffffffffu, s,  o);
        s2 += __shfl_xor_sync(0xffffffffu, s2, o);
    }
    __shared__ float rs1[8], rs2[8];
    if ((t & 31) == 0) { rs1[t >> 5] = s; rs2[t >> 5] = s2; }
    __syncthreads();
    float S = 0.f, S2 = 0.f;
    #pragma unroll
    for (int i = 0; i < 8; i++) { S += rs1[i]; S2 += rs2[i]; }
    float mu  = S * (1.0f / DIM);
    float var = S2 * (1.0f / DIM) - mu * mu;
    float rstd = rsqrtf(var + LN_EPS);
    int c = t * 4;
    float4 wv = *(const float4*)(w + c);
    float4 bv = *(const float4*)(bb + c);
    float o0 = (v.x - mu) * rstd * wv.x + bv.x;
    float o1 = (v.y - mu) * rstd * wv.y + bv.y;
    float o2 = (v.z - mu) * rstd * wv.z + bv.z;
    float o3 = (v.w - mu) * rstd * wv.w + bv.w;
    __half* dp = dst + (size_t)row * DIM + c;
    *(__half2*)(dp)     = __floats2half2_rn(o0, o1);
    *(__half2*)(dp + 2) = __floats2half2_rn(o2, o3);
}

/* ------------------- softmax stats ------------------- */
__global__ __launch_bounds__(256)
void k_stats()
{
    __shared__ float scol[8][NTOK];
    int z = blockIdx.y;
    int i0 = blockIdx.x * 128;
    const __half* plane = g_sim16 + (size_t)z * NTOK * NTOK;
    int t = threadIdx.x, w = t >> 5, lane = t & 31;

    float cacc[32];
    #pragma unroll
    for (int k = 0; k < 32; k++) cacc[k] = 0.f;

    for (int r = 0; r < 16; r++) {
        int i = i0 + w * 16 + r;
        const __half* rp = plane + (size_t)i * NTOK;
        float rsum = 0.f;
        #pragma unroll
        for (int k = 0; k < 8; k++) {
            float2 raw = *(const float2*)(rp + k * 128 + lane * 4);
            float2 f0 = __half22float2(*(__half2*)&raw.x);
            float2 f1 = __half22float2(*(__half2*)&raw.y);
            float e0 = __expf(f0.x), e1 = __expf(f0.y);
            float e2 = __expf(f1.x), e3 = __expf(f1.y);
            cacc[k*4+0] += e0; cacc[k*4+1] += e1;
            cacc[k*4+2] += e2; cacc[k*4+3] += e3;
            rsum += e0 + e1 + e2 + e3;
        }
        #pragma unroll
        for (int o = 16; o; o >>= 1) rsum += __shfl_xor_sync(0xffffffffu, rsum, o);
        if (lane == 0) g_rinv[z * NTOK + i] = 1.0f / rsum;
    }
    #pragma unroll
    for (int k = 0; k < 8; k++)
        *(float4*)&scol[w][k*128 + lane*4] =
            make_float4(cacc[k*4], cacc[k*4+1], cacc[k*4+2], cacc[k*4+3]);
    __syncthreads();
    float4 s = *(float4*)&scol[0][t*4];
    #pragma unroll
    for (int ww = 1; ww < 8; ww++) {
        float4 a = *(float4*)&scol[ww][t*4];
        s.x += a.x; s.y += a.y; s.z += a.z; s.w += a.w;
    }
    *(float4*)&g_cpart[((size_t)blockIdx.x * ZB + z) * NTOK + t*4] = s;
}

__global__ __launch_bounds__(256)
void k_colred()
{
    int idx = blockIdx.x * 256 + threadIdx.x;
    float S = 0.f;
    #pragma unroll
    for (int p = 0; p < 8; p++)
        S += g_cpart[(size_t)p * ZB * NTOK + idx];
    g_cinv[idx] = 1.0f / S;
}

/* ------------------- softmax + talking-heads mix ------------------- */
__global__ __launch_bounds__(256)
void k_mix(const float* __restrict__ thw, const float* __restrict__ cthw)
{
    __shared__ float sth[64], scth[64];
    if (threadIdx.x < 64) sth[threadIdx.x] = thw[threadIdx.x];
    else if (threadIdx.x < 128) scth[threadIdx.x - 64] = cthw[threadIdx.x - 64];
    __syncthreads();

    size_t idx = (size_t)blockIdx.x * blockDim.x + threadIdx.x;
    int j4 = (int)(idx & 255);
    int i  = (int)((idx >> 8) & 1023);
    int b  = (int)(idx >> 18);

    float4 pr[NHEAD], pc[NHEAD];
    #pragma unroll
    for (int h = 0; h < NHEAD; h++) {
        int zh = b * NHEAD + h;
        size_t off = ((size_t)zh * NTOK + i) * NTOK + j4 * 4;
        float2 raw = *(const float2*)(g_sim16 + off);
        float2 f0 = __half22float2(*(__half2*)&raw.x);
        float2 f1 = __half22float2(*(__half2*)&raw.y);
        float e0 = __expf(f0.x), e1 = __expf(f0.y);
        float e2 = __expf(f1.x), e3 = __expf(f1.y);
        float ri = g_rinv[zh * NTOK + i];
        pr[h] = make_float4(e0 * ri, e1 * ri, e2 * ri, e3 * ri);
        float4 cv = *(const float4*)(g_cinv + zh * NTOK + j4 * 4);
        pc[h] = make_float4(e0 * cv.x, e1 * cv.y, e2 * cv.z, e3 * cv.w);
    }
    #pragma unroll
    for (int g = 0; g < NHEAD; g++) {
        float4 a = make_float4(0.f, 0.f, 0.f, 0.f);
        float4 c = make_float4(0.f, 0.f, 0.f, 0.f);
        #pragma unroll
        for (int h = 0; h < NHEAD; h++) {
            float wa = sth[g * 8 + h], wc = scth[g * 8 + h];
            a.x += wa * pr[h].x; a.y += wa * pr[h].y;
            a.z += wa * pr[h].z; a.w += wa * pr[h].w;
            c.x += wc * pc[h].x; c.y += wc * pc[h].y;
            c.z += wc * pc[h].z; c.w += wc * pc[h].w;
        }
        size_t off = ((size_t)(b * NHEAD + g) * NTOK + i) * NTOK + j4 * 4;
        *(__half2*)(g_attn16 + off)     = __floats2half2_rn(a.x, a.y);
        *(__half2*)(g_attn16 + off + 2) = __floats2half2_rn(a.z, a.w);
        *(__half2*)(g_ctx16 + off)      = __floats2half2_rn(c.x, c.y);
        *(__half2*)(g_ctx16 + off + 2)  = __floats2half2_rn(c.z, c.w);
    }
}

/* ------------------- launch ------------------- */
extern "C" void kernel_launch(void* const* d_in, const int* in_sizes, int n_in,
                              void* d_out, int out_size)
{
    const float* x    = (const float*)d_in[0];
    const float* ci   = (const float*)d_in[1];
    const float* ref  = (const float*)d_in[2];
    const float* lnw  = (const float*)d_in[3];
    const float* lnb  = (const float*)d_in[4];
    const float* clw  = (const float*)d_in[5];
    const float* clb  = (const float*)d_in[6];
    const float* Wk   = (const float*)d_in[7];
    const float* Wv   = (const float*)d_in[8];
    const float* Wo   = (const float*)d_in[9];
    const float* bo   = (const float*)d_in[10];
    const float* thw  = (const float*)d_in[11];
    const float* cthw = (const float*)d_in[12];

    float* out1 = (float*)d_out;
    float* out2 = (float*)d_out + (size_t)ROWS * DIM;

    __half *xn, *cn, *rn, *cond, *refv, *outpre, *attn, *ctx, *wk16, *wv16, *wo16, *sim;
    cudaGetSymbolAddress((void**)&xn, g_xn16);
    cudaGetSymbolAddress((void**)&cn, g_cn16);
    cudaGetSymbolAddress((void**)&rn, g_rn16);
    cudaGetSymbolAddress((void**)&cond, g_cond16);
    cudaGetSymbolAddress((void**)&refv, g_refv16);
    cudaGetSymbolAddress((void**)&outpre, g_outpre16);
    cudaGetSymbolAddress((void**)&attn, g_attn16);
    cudaGetSymbolAddress((void**)&ctx, g_ctx16);
    cudaGetSymbolAddress((void**)&wk16, g_Wk16);
    cudaGetSymbolAddress((void**)&wv16, g_Wv16);
    cudaGetSymbolAddress((void**)&wo16, g_Wo16);
    cudaGetSymbolAddress((void**)&sim, g_sim16);

    /* dynamic smem (bytes): 3 stages */
    const int SM_A0B0 = 3 * (256*40 + 32*136) * 2;  /* 87552 */
    const int SM_A0B1 = 3 * (256*40 + 128*40) * 2;  /* 92160 */
    const int SM_A1B0 = 3 * (32*264 + 32*136) * 2;  /* 76800 */

    cudaFuncSetAttribute((const void*)k_hgemm<0,0,3,2>, cudaFuncAttributeMaxDynamicSharedMemorySize, SM_A0B0);
    cudaFuncSetAttribute((const void*)k_hgemm<0,0,2,2>, cudaFuncAttributeMaxDynamicSharedMemorySize, SM_A0B0);
    cudaFuncSetAttribute((const void*)k_hgemm<0,1,1,4>, cudaFuncAttributeMaxDynamicSharedMemorySize, SM_A0B1);
    cudaFuncSetAttribute((const void*)k_hgemm<0,0,1,2>, cudaFuncAttributeMaxDynamicSharedMemorySize, SM_A0B0);
    cudaFuncSetAttribute((const void*)k_hgemm<1,0,1,0>, cudaFuncAttributeMaxDynamicSharedMemorySize, SM_A1B0);
    cudaFuncSetAttribute((const void*)k_hgemm<0,0,1,3>, cudaFuncAttributeMaxDynamicSharedMemorySize, SM_A0B0);

    /* 0. weights -> f16 (native layouts) */
    k_f2h<<<(3*DIM*DIM)/1024, 256>>>(Wk, wk16, 3*DIM*DIM);
    k_f2h<<<(2*DIM*DIM)/1024, 256>>>(Wv, wv16, 2*DIM*DIM);
    k_f2h<<<(DIM*DIM)/1024, 256>>>(Wo, wo16, DIM*DIM);

    /* 1. LayerNorms -> f16 */
    k_layernorm<<<dim3(ROWS, 3), 256>>>(x, ci, ref, lnw, lnb, clw, clb);

    /* 2. cond = [xn|cn|rn] @ Wk (K=3072) */
    k_hgemm<0,0,3,2><<<dim3(DIM/128, ROWS/256, 1), 256, SM_A0B0>>>(
        xn, cn, rn, DIM, wk16, DIM, nullptr, cond, DIM, 3*DIM, nullptr,
        0, 0, 0, 0, 0, 0);

    /* 3. refv = [xn|rn] @ Wv (K=2048) */
    k_hgemm<0,0,2,2><<<dim3(DIM/128, ROWS/256, 1), 256, SM_A0B0>>>(
        xn, rn, nullptr, DIM, wv16, DIM, nullptr, refv, DIM, 2*DIM, nullptr,
        0, 0, 0, 0, 0, 0);

    /* 4. sim = scale * cond @ refv^T per (b,h) -> f16 */
    k_hgemm<0,1,1,4><<<dim3(NTOK/128, NTOK/256, ZB), 256, SM_A0B1>>>(
        cond, nullptr, nullptr, DIM, refv, DIM, nullptr, sim, NTOK, DHEAD, nullptr,
        (size_t)NTOK*DIM, DHEAD,
        (size_t)NTOK*DIM, DHEAD,
        (size_t)NHEAD*NTOK*NTOK, (size_t)NTOK*NTOK);

    /* 5. stats + col reduce */
    k_stats<<<dim3(8, ZB), 256>>>();
    k_colred<<<(ZB*NTOK)/256, 256>>>();

    /* 6. softmax + talking-heads -> f16 */
    k_mix<<<(BATCH * NTOK * (NTOK / 4)) / 256, 256>>>(thw, cthw);

    /* 7. outpre = attn @ refv per (b,g) */
    k_hgemm<0,0,1,2><<<dim3(DHEAD/128, NTOK/256, ZB), 256, SM_A0B0>>>(
        attn, nullptr, nullptr, NTOK, refv, DIM, nullptr, outpre, DIM, NTOK, nullptr,
        (size_t)NHEAD*NTOK*NTOK, (size_t)NTOK*NTOK,
        (size_t)NTOK*DIM, DHEAD,
        (size_t)NTOK*DIM, DHEAD);

    /* 8. out2 = ctx^T @ cond per (b,g) */
    k_hgemm<1,0,1,0><<<dim3(DHEAD/128, NTOK/256, ZB), 256, SM_A1B0>>>(
        ctx, nullptr, nullptr, NTOK, cond, DIM, out2, nullptr, DIM, NTOK, nullptr,
        (size_t)NHEAD*NTOK*NTOK, (size_t)NTOK*NTOK,
        (size_t)NTOK*DIM, DHEAD,
        (size_t)NTOK*DIM, DHEAD);

    /* 9. out1 = outpre @ Wo + bo */
    k_hgemm<0,0,1,3><<<dim3(DIM/128, ROWS/256, 1), 256, SM_A0B0>>>(
        outpre, nullptr, nullptr, DIM, wo16, DIM, out1, nullptr, DIM, DIM, bo,
        0, 0, 0, 0, 0, 0);
}

// round 13
// speedup vs baseline: 1.0972x; 1.0972x over previous
#include <cuda_runtime.h>
#include <cuda_fp16.h>
#include <math.h>
#include <stdint.h>

#define BATCH 4
#define NTOK 1024
#define DIM 1024
#define NHEAD 8
#define DHEAD 128
#define ROWS (BATCH*NTOK)
#define ZB (BATCH*NHEAD)
#define ATTN_SCALE 0.08838834764831845f
#define LN_EPS 1e-5f

/* ------------------- device scratch ------------------- */
__device__ __half g_xn16[ROWS*DIM];
__device__ __half g_cn16[ROWS*DIM];
__device__ __half g_rn16[ROWS*DIM];
__device__ __half g_cond16[ROWS*DIM];
__device__ __half g_refv16[ROWS*DIM];
__device__ __half g_outpre16[ROWS*DIM];
__device__ __half g_attn16[(size_t)ZB*NTOK*NTOK];
__device__ __half g_ctx16[(size_t)ZB*NTOK*NTOK];
__device__ __half g_sim16[(size_t)ZB*NTOK*NTOK];
__device__ __half g_Wk16[3*DIM*DIM];
__device__ __half g_Wv16[2*DIM*DIM];
__device__ __half g_Wo16[DIM*DIM];
__device__ float  g_rinv[ZB*NTOK];
__device__ float  g_cinv[ZB*NTOK];
__device__ float  g_cpart[8*ZB*NTOK];

/* ------------------- asm helpers ------------------- */
__device__ __forceinline__ uint32_t smaddr(const void* p) {
    return (uint32_t)__cvta_generic_to_shared(p);
}
__device__ __forceinline__ void ldsm4(uint32_t& r0, uint32_t& r1, uint32_t& r2, uint32_t& r3, uint32_t a) {
    asm volatile("ldmatrix.sync.aligned.m8n8.x4.shared.b16 {%0,%1,%2,%3},[%4];"
        : "=r"(r0), "=r"(r1), "=r"(r2), "=r"(r3) : "r"(a));
}
__device__ __forceinline__ void ldsm4t(uint32_t& r0, uint32_t& r1, uint32_t& r2, uint32_t& r3, uint32_t a) {
    asm volatile("ldmatrix.sync.aligned.m8n8.x4.trans.shared.b16 {%0,%1,%2,%3},[%4];"
        : "=r"(r0), "=r"(r1), "=r"(r2), "=r"(r3) : "r"(a));
}
__device__ __forceinline__ void mma_f16(float c[4], const uint32_t a[4], const uint32_t b[2]) {
    asm volatile(
        "mma.sync.aligned.m16n8k16.row.col.f32.f16.f16.f32 "
        "{%0,%1,%2,%3},{%4,%5,%6,%7},{%8,%9},{%0,%1,%2,%3};"
        : "+f"(c[0]), "+f"(c[1]), "+f"(c[2]), "+f"(c[3])
        : "r"(a[0]), "r"(a[1]), "r"(a[2]), "r"(a[3]), "r"(b[0]), "r"(b[1]));
}
__device__ __forceinline__ void cp_async16(void* smem_dst, const void* gsrc) {
    uint32_t d = smaddr(smem_dst);
    asm volatile("cp.async.cg.shared.global [%0], [%1], 16;" :: "r"(d), "l"(gsrc));
}
#define CP_COMMIT() asm volatile("cp.async.commit_group;")
#define CP_WAIT(n)  asm volatile("cp.async.wait_group %0;" :: "n"(n))

/* ------------------------------------------------------------------ */
/* f16 mma.sync GEMM: CTA 128x128, BK=64, 3-stage cp.async, 8 warps,   */
/* warp tile 64x32 (proven R4 shape), 4 ks-steps per barrier.          */
/* AL: 0 = A [m][k], 1 = A [k][m]. BL: 0 = B [k][n], 1 = B [n][k].     */
/* EPI: 0 f32, 2 f16, 3 f32+bias, 4 f16*scale                          */
/* ------------------------------------------------------------------ */
template<int AL, int BL, int NSEG, int EPI>
__global__ __launch_bounds__(256)
void k_hgemm(const __half* __restrict__ A0, const __half* __restrict__ A1,
             const __half* __restrict__ A2, int lda,
             const __half* __restrict__ B, int ldb,
             float* __restrict__ Cf, __half* __restrict__ Ch, int ldc, int Ktot,
             const float* __restrict__ bias,
             size_t sAb, size_t sAh, size_t sBb, size_t sBh,
             size_t sCb, size_t sCh)
{
    constexpr int PA = AL ? 136 : 72;              /* pitch (halves) */
    constexpr int PB = BL ? 72 : 136;
    constexpr int ASZ = AL ? 64*136 : 128*72;      /* halves per stage */
    constexpr int BSZ = BL ? 128*72 : 64*136;
    constexpr int STG = 3;

    extern __shared__ __half sm16[];
    __half* Asm = sm16;
    __half* Bsm = sm16 + STG*ASZ;

    const int z = blockIdx.z, zb = z >> 3, zh = z & 7;
    const __half* Az = A0 + zb*sAb + zh*sAh;
    const __half* Bz = B  + zb*sBb + zh*sBh;

    const int tid = threadIdx.x;
    const int bm = blockIdx.y, bn = blockIdx.x;
    const int NIT = Ktot >> 6;

    const int wid = tid >> 5, lane = tid & 31;
    const int gid = lane >> 2, tig = lane & 3;
    const int wm = (wid >> 2) * 64, wn = (wid & 3) * 32;

    float acc[4][4][4];
    #pragma unroll
    for (int i = 0; i < 4; i++)
        #pragma unroll
        for (int j = 0; j < 4; j++)
            #pragma unroll
            for (int k = 0; k < 4; k++) acc[i][j][k] = 0.f;

    auto load_stage = [&](int st, int it) {
        const int k0 = it << 6;
        __half* as = Asm + st*ASZ;
        __half* bs = Bsm + st*BSZ;
        const __half* Ap = Az;
        int kc = k0;
        if (NSEG > 1) {
            int s = k0 >> 10;
            Ap = (s == 0) ? A0 : (s == 1) ? A1 : A2;
            kc = k0 & 1023;
        }
        #pragma unroll
        for (int j = 0; j < 4; j++) {
            int id = tid + j*256;
            if (AL == 0) {
                int r = id >> 3, c = (id & 7) * 8;       /* 128 x 64 */
                cp_async16(as + r*PA + c, Ap + (size_t)(bm*128 + r)*lda + kc + c);
            } else {
                int r = id >> 4, c = (id & 15) * 8;      /* 64 x 128 */
                cp_async16(as + r*PA + c, Az + (size_t)(k0 + r)*lda + bm*128 + c);
            }
        }
        #pragma unroll
        for (int j = 0; j < 4; j++) {
            int id = tid + j*256;
            if (BL == 0) {
                int r = id >> 4, c = (id & 15) * 8;      /* 64 x 128 */
                cp_async16(bs + r*PB + c, Bz + (size_t)(k0 + r)*ldb + bn*128 + c);
            } else {
                int r = id >> 3, c = (id & 7) * 8;       /* 128 x 64 */
                cp_async16(bs + r*PB + c, Bz + (size_t)(bn*128 + r)*ldb + k0 + c);
            }
        }
    };

    auto compute_stage = [&](int st) {
        const __half* as = Asm + st*ASZ;
        const __half* bs = Bsm + st*BSZ;
        const int g8 = lane >> 3, i8 = lane & 7;
        #pragma unroll
        for (int ks = 0; ks < 4; ks++) {
            uint32_t af[4][4];
            #pragma unroll
            for (int mt = 0; mt < 4; mt++) {
                if (AL == 0) {
                    uint32_t a = smaddr(as + (wm + mt*16 + (lane & 15))*PA + ks*16 + (lane >> 4)*8);
                    ldsm4(af[mt][0], af[mt][1], af[mt][2], af[mt][3], a);
                } else {
                    uint32_t a = smaddr(as + (ks*16 + (g8 >> 1)*8 + i8)*PA + wm + mt*16 + (g8 & 1)*8);
                    ldsm4t(af[mt][0], af[mt][1], af[mt][2], af[mt][3], a);
                }
            }
            uint32_t bf[4][2];
            #pragma unroll
            for (int p = 0; p < 2; p++) {
                uint32_t q0, q1, q2, q3;
                if (BL == 1) {
                    uint32_t a = smaddr(bs + (wn + p*16 + (g8 >> 1)*8 + i8)*PB + ks*16 + (g8 & 1)*8);
                    ldsm4(q0, q1, q2, q3, a);
                } else {
                    uint32_t a = smaddr(bs + (ks*16 + (g8 & 1)*8 + i8)*PB + wn + p*16 + (g8 >> 1)*8);
                    ldsm4t(q0, q1, q2, q3, a);
                }
                bf[2*p][0] = q0; bf[2*p][1] = q1;
                bf[2*p+1][0] = q2; bf[2*p+1][1] = q3;
            }
            #pragma unroll
            for (int mt = 0; mt < 4; mt++)
                #pragma unroll
                for (int nt = 0; nt < 4; nt++)
                    mma_f16(acc[mt][nt], af[mt], bf[nt]);
        }
    };

    load_stage(0, 0); CP_COMMIT();
    if (NIT > 1) { load_stage(1, 1); CP_COMMIT(); }
    int buf = 0;
    for (int it = 0; it < NIT; ++it) {
        if (it + 1 < NIT) { CP_WAIT(1); } else { CP_WAIT(0); }
        __syncthreads();
        if (it + 2 < NIT) load_stage((buf + 2 >= STG) ? buf + 2 - STG : buf + 2, it + 2);
        CP_COMMIT();
        compute_stage(buf);
        buf = (buf + 1 >= STG) ? buf + 1 - STG : buf + 1;
    }

    /* epilogue */
    float* Cfz = (EPI == 0 || EPI == 3) ? Cf + zb*sCb + zh*sCh : nullptr;
    __half* Chz = (EPI == 2 || EPI == 4) ? Ch + zb*sCb + zh*sCh : nullptr;
    #pragma unroll
    for (int mt = 0; mt < 4; mt++) {
        #pragma unroll
        for (int nt = 0; nt < 4; nt++) {
            int r0  = bm*128 + wm + mt*16 + gid;
            int col = bn*128 + wn + nt*8 + 2*tig;
            float c0 = acc[mt][nt][0], c1 = acc[mt][nt][1];
            float c2 = acc[mt][nt][2], c3 = acc[mt][nt][3];
            if (EPI == 4) { c0 *= ATTN_SCALE; c1 *= ATTN_SCALE; c2 *= ATTN_SCALE; c3 *= ATTN_SCALE; }
            if (EPI == 3) {
                float2 bv = *(const float2*)(bias + col);
                c0 += bv.x; c1 += bv.y; c2 += bv.x; c3 += bv.y;
            }
            if (EPI == 2 || EPI == 4) {
                *(__half2*)&Chz[(size_t)r0*ldc + col]     = __floats2half2_rn(c0, c1);
                *(__half2*)&Chz[(size_t)(r0+8)*ldc + col] = __floats2half2_rn(c2, c3);
            } else {
                *(float2*)&Cfz[(size_t)r0*ldc + col]     = make_float2(c0, c1);
                *(float2*)&Cfz[(size_t)(r0+8)*ldc + col] = make_float2(c2, c3);
            }
        }
    }
}

/* ------------------- f32 -> f16 convert ------------------- */
__global__ __launch_bounds__(256)
void k_f2h(const float* __restrict__ s, __half* __restrict__ d, int n)
{
    int i = (blockIdx.x * 256 + threadIdx.x) * 4;
    if (i < n) {
        float4 v = *(const float4*)(s + i);
        *(__half2*)(d + i)     = __floats2half2_rn(v.x, v.y);
        *(__half2*)(d + i + 2) = __floats2half2_rn(v.z, v.w);
    }
}

/* ------------------- LayerNorm -> f16 ------------------- */
__global__ __launch_bounds__(256)
void k_layernorm(const float* __restrict__ x, const float* __restrict__ ci,
                 const float* __restrict__ ref,
                 const float* __restrict__ lw, const float* __restrict__ lb,
                 const float* __restrict__ cw, const float* __restrict__ cb)
{
    int row = blockIdx.x;
    int which = blockIdx.y;
    const float* src = (which == 0) ? x : (which == 1) ? ref : ci;
    const float* w   = (which == 2) ? cw : lw;
    const float* bb  = (which == 2) ? cb : lb;
    __half* dst      = (which == 0) ? g_xn16 : (which == 1) ? g_rn16 : g_cn16;

    const float* p = src + (size_t)row * DIM;
    int t = threadIdx.x;
    float4 v = *(const float4*)(p + t * 4);
    float s  = v.x + v.y + v.z + v.w;
    float s2 = v.x*v.x + v.y*v.y + v.z*v.z + v.w*v.w;
    for (int o = 16; o; o >>= 1) {
        s  += __shfl_xor_sync(0xffffffffu, s,  o);
        s2 += __shfl_xor_sync(0xffffffffu, s2, o);
    }
    __shared__ float rs1[8], rs2[8];
    if ((t & 31) == 0) { rs1[t >> 5] = s; rs2[t >> 5] = s2; }
    __syncthreads();
    float S = 0.f, S2 = 0.f;
    #pragma unroll
    for (int i = 0; i < 8; i++) { S += rs1[i]; S2 += rs2[i]; }
    float mu  = S * (1.0f / DIM);
    float var = S2 * (1.0f / DIM) - mu * mu;
    float rstd = rsqrtf(var + LN_EPS);
    int c = t * 4;
    float4 wv = *(const float4*)(w + c);
    float4 bv = *(const float4*)(bb + c);
    float o0 = (v.x - mu) * rstd * wv.x + bv.x;
    float o1 = (v.y - mu) * rstd * wv.y + bv.y;
    float o2 = (v.z - mu) * rstd * wv.z + bv.z;
    float o3 = (v.w - mu) * rstd * wv.w + bv.w;
    __half* dp = dst + (size_t)row * DIM + c;
    *(__half2*)(dp)     = __floats2half2_rn(o0, o1);
    *(__half2*)(dp + 2) = __floats2half2_rn(o2, o3);
}

/* ------------------- softmax stats ------------------- */
__global__ __launch_bounds__(256)
void k_stats()
{
    __shared__ float scol[8][NTOK];
    int z = blockIdx.y;
    int i0 = blockIdx.x * 128;
    const __half* plane = g_sim16 + (size_t)z * NTOK * NTOK;
    int t = threadIdx.x, w = t >> 5, lane = t & 31;

    float cacc[32];
    #pragma unroll
    for (int k = 0; k < 32; k++) cacc[k] = 0.f;

    for (int r = 0; r < 16; r++) {
        int i = i0 + w * 16 + r;
        const __half* rp = plane + (size_t)i * NTOK;
        float rsum = 0.f;
        #pragma unroll
        for (int k = 0; k < 8; k++) {
            float2 raw = *(const float2*)(rp + k * 128 + lane * 4);
            float2 f0 = __half22float2(*(__half2*)&raw.x);
            float2 f1 = __half22float2(*(__half2*)&raw.y);
            float e0 = __expf(f0.x), e1 = __expf(f0.y);
            float e2 = __expf(f1.x), e3 = __expf(f1.y);
            cacc[k*4+0] += e0; cacc[k*4+1] += e1;
            cacc[k*4+2] += e2; cacc[k*4+3] += e3;
            rsum += e0 + e1 + e2 + e3;
        }
        #pragma unroll
        for (int o = 16; o; o >>= 1) rsum += __shfl_xor_sync(0xffffffffu, rsum, o);
        if (lane == 0) g_rinv[z * NTOK + i] = 1.0f / rsum;
    }
    #pragma unroll
    for (int k = 0; k < 8; k++)
        *(float4*)&scol[w][k*128 + lane*4] =
            make_float4(cacc[k*4], cacc[k*4+1], cacc[k*4+2], cacc[k*4+3]);
    __syncthreads();
    float4 s = *(float4*)&scol[0][t*4];
    #pragma unroll
    for (int ww = 1; ww < 8; ww++) {
        float4 a = *(float4*)&scol[ww][t*4];
        s.x += a.x; s.y += a.y; s.z += a.z; s.w += a.w;
    }
    *(float4*)&g_cpart[((size_t)blockIdx.x * ZB + z) * NTOK + t*4] = s;
}

__global__ __launch_bounds__(256)
void k_colred()
{
    int idx = blockIdx.x * 256 + threadIdx.x;
    float S = 0.f;
    #pragma unroll
    for (int p = 0; p < 8; p++)
        S += g_cpart[(size_t)p * ZB * NTOK + idx];
    g_cinv[idx] = 1.0f / S;
}

/* ------------------- softmax + talking-heads mix ------------------- */
__global__ __launch_bounds__(256)
void k_mix(const float* __restrict__ thw, const float* __restrict__ cthw)
{
    __shared__ float sth[64], scth[64];
    if (threadIdx.x < 64) sth[threadIdx.x] = thw[threadIdx.x];
    else if (threadIdx.x < 128) scth[threadIdx.x - 64] = cthw[threadIdx.x - 64];
    __syncthreads();

    size_t idx = (size_t)blockIdx.x * blockDim.x + threadIdx.x;
    int j4 = (int)(idx & 255);
    int i  = (int)((idx >> 8) & 1023);
    int b  = (int)(idx >> 18);

    float4 pr[NHEAD], pc[NHEAD];
    #pragma unroll
    for (int h = 0; h < NHEAD; h++) {
        int zh = b * NHEAD + h;
        size_t off = ((size_t)zh * NTOK + i) * NTOK + j4 * 4;
        float2 raw = *(const float2*)(g_sim16 + off);
        float2 f0 = __half22float2(*(__half2*)&raw.x);
        float2 f1 = __half22float2(*(__half2*)&raw.y);
        float e0 = __expf(f0.x), e1 = __expf(f0.y);
        float e2 = __expf(f1.x), e3 = __expf(f1.y);
        float ri = g_rinv[zh * NTOK + i];
        pr[h] = make_float4(e0 * ri, e1 * ri, e2 * ri, e3 * ri);
        float4 cv = *(const float4*)(g_cinv + zh * NTOK + j4 * 4);
        pc[h] = make_float4(e0 * cv.x, e1 * cv.y, e2 * cv.z, e3 * cv.w);
    }
    #pragma unroll
    for (int g = 0; g < NHEAD; g++) {
        float4 a = make_float4(0.f, 0.f, 0.f, 0.f);
        float4 c = make_float4(0.f, 0.f, 0.f, 0.f);
        #pragma unroll
        for (int h = 0; h < NHEAD; h++) {
            float wa = sth[g * 8 + h], wc = scth[g * 8 + h];
            a.x += wa * pr[h].x; a.y += wa * pr[h].y;
            a.z += wa * pr[h].z; a.w += wa * pr[h].w;
            c.x += wc * pc[h].x; c.y += wc * pc[h].y;
            c.z += wc * pc[h].z; c.w += wc * pc[h].w;
        }
        size_t off = ((size_t)(b * NHEAD + g) * NTOK + i) * NTOK + j4 * 4;
        *(__half2*)(g_attn16 + off)     = __floats2half2_rn(a.x, a.y);
        *(__half2*)(g_attn16 + off + 2) = __floats2half2_rn(a.z, a.w);
        *(__half2*)(g_ctx16 + off)      = __floats2half2_rn(c.x, c.y);
        *(__half2*)(g_ctx16 + off + 2)  = __floats2half2_rn(c.z, c.w);
    }
}

/* ------------------- launch ------------------- */
extern "C" void kernel_launch(void* const* d_in, const int* in_sizes, int n_in,
                              void* d_out, int out_size)
{
    const float* x    = (const float*)d_in[0];
    const float* ci   = (const float*)d_in[1];
    const float* ref  = (const float*)d_in[2];
    const float* lnw  = (const float*)d_in[3];
    const float* lnb  = (const float*)d_in[4];
    const float* clw  = (const float*)d_in[5];
    const float* clb  = (const float*)d_in[6];
    const float* Wk   = (const float*)d_in[7];
    const float* Wv   = (const float*)d_in[8];
    const float* Wo   = (const float*)d_in[9];
    const float* bo   = (const float*)d_in[10];
    const float* thw  = (const float*)d_in[11];
    const float* cthw = (const float*)d_in[12];

    float* out1 = (float*)d_out;
    float* out2 = (float*)d_out + (size_t)ROWS * DIM;

    __half *xn, *cn, *rn, *cond, *refv, *outpre, *attn, *ctx, *wk16, *wv16, *wo16, *sim;
    cudaGetSymbolAddress((void**)&xn, g_xn16);
    cudaGetSymbolAddress((void**)&cn, g_cn16);
    cudaGetSymbolAddress((void**)&rn, g_rn16);
    cudaGetSymbolAddress((void**)&cond, g_cond16);
    cudaGetSymbolAddress((void**)&refv, g_refv16);
    cudaGetSymbolAddress((void**)&outpre, g_outpre16);
    cudaGetSymbolAddress((void**)&attn, g_attn16);
    cudaGetSymbolAddress((void**)&ctx, g_ctx16);
    cudaGetSymbolAddress((void**)&wk16, g_Wk16);
    cudaGetSymbolAddress((void**)&wv16, g_Wv16);
    cudaGetSymbolAddress((void**)&wo16, g_Wo16);
    cudaGetSymbolAddress((void**)&sim, g_sim16);

    /* dynamic smem (bytes): 3 stages, BK=64 */
    const int SM_MK_KN = 3 * (128*72 + 64*136) * 2;  /* 107520 */
    const int SM_MK_NK = 3 * (128*72 + 128*72) * 2;  /* 110592 */
    const int SM_KM_KN = 3 * (64*136 + 64*136) * 2;  /* 104448 */

    cudaFuncSetAttribute((const void*)k_hgemm<0,0,3,2>, cudaFuncAttributeMaxDynamicSharedMemorySize, SM_MK_KN);
    cudaFuncSetAttribute((const void*)k_hgemm<0,0,2,2>, cudaFuncAttributeMaxDynamicSharedMemorySize, SM_MK_KN);
    cudaFuncSetAttribute((const void*)k_hgemm<0,1,1,4>, cudaFuncAttributeMaxDynamicSharedMemorySize, SM_MK_NK);
    cudaFuncSetAttribute((const void*)k_hgemm<0,0,1,2>, cudaFuncAttributeMaxDynamicSharedMemorySize, SM_MK_KN);
    cudaFuncSetAttribute((const void*)k_hgemm<1,0,1,0>, cudaFuncAttributeMaxDynamicSharedMemorySize, SM_KM_KN);
    cudaFuncSetAttribute((const void*)k_hgemm<0,0,1,3>, cudaFuncAttributeMaxDynamicSharedMemorySize, SM_MK_KN);

    /* 0. weights -> f16 */
    k_f2h<<<(3*DIM*DIM)/1024, 256>>>(Wk, wk16, 3*DIM*DIM);
    k_f2h<<<(2*DIM*DIM)/1024, 256>>>(Wv, wv16, 2*DIM*DIM);
    k_f2h<<<(DIM*DIM)/1024, 256>>>(Wo, wo16, DIM*DIM);

    /* 1. LayerNorms -> f16 */
    k_layernorm<<<dim3(ROWS, 3), 256>>>(x, ci, ref, lnw, lnb, clw, clb);

    /* 2. cond = [xn|cn|rn] @ Wk (K=3072) */
    k_hgemm<0,0,3,2><<<dim3(DIM/128, ROWS/128, 1), 256, SM_MK_KN>>>(
        xn, cn, rn, DIM, wk16, DIM, nullptr, cond, DIM, 3*DIM, nullptr,
        0, 0, 0, 0, 0, 0);

    /* 3. refv = [xn|rn] @ Wv (K=2048) */
    k_hgemm<0,0,2,2><<<dim3(DIM/128, ROWS/128, 1), 256, SM_MK_KN>>>(
        xn, rn, nullptr, DIM, wv16, DIM, nullptr, refv, DIM, 2*DIM, nullptr,
        0, 0, 0, 0, 0, 0);

    /* 4. sim = scale * cond @ refv^T per (b,h) -> f16 (K=128) */
    k_hgemm<0,1,1,4><<<dim3(NTOK/128, NTOK/128, ZB), 256, SM_MK_NK>>>(
        cond, nullptr, nullptr, DIM, refv, DIM, nullptr, sim, NTOK, DHEAD, nullptr,
        (size_t)NTOK*DIM, DHEAD,
        (size_t)NTOK*DIM, DHEAD,
        (size_t)NHEAD*NTOK*NTOK, (size_t)NTOK*NTOK);

    /* 5. stats + col reduce */
    k_stats<<<dim3(8, ZB), 256>>>();
    k_colred<<<(ZB*NTOK)/256, 256>>>();

    /* 6. softmax + talking-heads -> f16 */
    k_mix<<<(BATCH * NTOK * (NTOK / 4)) / 256, 256>>>(thw, cthw);

    /* 7. outpre = attn @ refv per (b,g) (K=1024) */
    k_hgemm<0,0,1,2><<<dim3(DHEAD/128, NTOK/128, ZB), 256, SM_MK_KN>>>(
        attn, nullptr, nullptr, NTOK, refv, DIM, nullptr, outpre, DIM, NTOK, nullptr,
        (size_t)NHEAD*NTOK*NTOK, (size_t)NTOK*NTOK,
        (size_t)NTOK*DIM, DHEAD,
        (size_t)NTOK*DIM, DHEAD);

    /* 8. out2 = ctx^T @ cond per (b,g) (K=1024) */
    k_hgemm<1,0,1,0><<<dim3(DHEAD/128, NTOK/128, ZB), 256, SM_KM_KN>>>(
        ctx, nullptr, nullptr, NTOK, cond, DIM, out2, nullptr, DIM, NTOK, nullptr,
        (size_t)NHEAD*NTOK*NTOK, (size_t)NTOK*NTOK,
        (size_t)NTOK*DIM, DHEAD,
        (size_t)NTOK*DIM, DHEAD);

    /* 9. out1 = outpre @ Wo + bo (K=1024) */
    k_hgemm<0,0,1,3><<<dim3(DIM/128, ROWS/128, 1), 256, SM_MK_KN>>>(
        outpre, nullptr, nullptr, DIM, wo16, DIM, out1, nullptr, DIM, DIM, bo,
        0, 0, 0, 0, 0, 0);
}

// round 14
// speedup vs baseline: 1.2283x; 1.1196x over previous
#include <cuda_runtime.h>
#include <cuda_fp16.h>
#include <math.h>
#include <stdint.h>

#define BATCH 4
#define NTOK 1024
#define DIM 1024
#define NHEAD 8
#define DHEAD 128
#define ROWS (BATCH*NTOK)
#define ZB (BATCH*NHEAD)
#define ZBN (ZB*NTOK)
#define ATTN_SCALE 0.08838834764831845f
#define LN_EPS 1e-5f

/* ------------------- device scratch ------------------- */
__device__ __half g_xn16[ROWS*DIM];
__device__ __half g_cn16[ROWS*DIM];
__device__ __half g_rn16[ROWS*DIM];
__device__ __half g_cond16[ROWS*DIM];
__device__ __half g_refv16[ROWS*DIM];
__device__ __half g_outpre16[ROWS*DIM];
__device__ __half g_attn16[(size_t)ZB*NTOK*NTOK];
__device__ __half g_ctx16[(size_t)ZB*NTOK*NTOK];
__device__ __half g_sim16[(size_t)ZB*NTOK*NTOK];
__device__ __half g_Wk16[3*DIM*DIM];
__device__ __half g_Wv16[2*DIM*DIM];
__device__ __half g_Wo16[DIM*DIM];
__device__ float  g_rinv[ZBN];
__device__ float  g_cinv[ZBN];
__device__ float  g_rpart[8*ZBN];
__device__ float  g_cpart[8*ZBN];

/* ------------------- asm helpers ------------------- */
__device__ __forceinline__ uint32_t smaddr(const void* p) {
    return (uint32_t)__cvta_generic_to_shared(p);
}
__device__ __forceinline__ void ldsm4(uint32_t& r0, uint32_t& r1, uint32_t& r2, uint32_t& r3, uint32_t a) {
    asm volatile("ldmatrix.sync.aligned.m8n8.x4.shared.b16 {%0,%1,%2,%3},[%4];"
        : "=r"(r0), "=r"(r1), "=r"(r2), "=r"(r3) : "r"(a));
}
__device__ __forceinline__ void ldsm4t(uint32_t& r0, uint32_t& r1, uint32_t& r2, uint32_t& r3, uint32_t a) {
    asm volatile("ldmatrix.sync.aligned.m8n8.x4.trans.shared.b16 {%0,%1,%2,%3},[%4];"
        : "=r"(r0), "=r"(r1), "=r"(r2), "=r"(r3) : "r"(a));
}
__device__ __forceinline__ void mma_f16(float c[4], const uint32_t a[4], const uint32_t b[2]) {
    asm volatile(
        "mma.sync.aligned.m16n8k16.row.col.f32.f16.f16.f32 "
        "{%0,%1,%2,%3},{%4,%5,%6,%7},{%8,%9},{%0,%1,%2,%3};"
        : "+f"(c[0]), "+f"(c[1]), "+f"(c[2]), "+f"(c[3])
        : "r"(a[0]), "r"(a[1]), "r"(a[2]), "r"(a[3]), "r"(b[0]), "r"(b[1]));
}
__device__ __forceinline__ void cp_async16(void* smem_dst, const void* gsrc) {
    uint32_t d = smaddr(smem_dst);
    asm volatile("cp.async.cg.shared.global [%0], [%1], 16;" :: "r"(d), "l"(gsrc));
}
#define CP_COMMIT() asm volatile("cp.async.commit_group;")
#define CP_WAIT(n)  asm volatile("cp.async.wait_group %0;" :: "n"(n))

/* ------------------------------------------------------------------ */
/* GEMM body: CTA 128x128, BK=64, 3-stage cp.async, 8 warps, 64x32 wt. */
/* AL: 0 = A [m][k], 1 = A [k][m]. BL: 0 = B [k][n], 1 = B [n][k].     */
/* EPI: 0 f32, 2 f16, 3 f32+bias, 4 f16*scale + fused softmax stats    */
/* ------------------------------------------------------------------ */
template<int AL, int BL, int NSEG, int EPI>
__device__ __forceinline__
void hgemm_body(const __half* __restrict__ A0, const __half* __restrict__ A1,
                const __half* __restrict__ A2, int lda,
                const __half* __restrict__ Bz, int ldb,
                float* __restrict__ Cfz, __half* __restrict__ Chz, int ldc,
                int Ktot, const float* __restrict__ bias,
                int z, int bm, int bn)
{
    constexpr int PA = AL ? 136 : 72;
    constexpr int PB = BL ? 72 : 136;
    constexpr int ASZ = AL ? 64*136 : 128*72;
    constexpr int BSZ = BL ? 128*72 : 64*136;
    constexpr int STG = 3;

    extern __shared__ __half sm16[];
    __half* Asm = sm16;
    __half* Bsm = sm16 + STG*ASZ;

    const int tid = threadIdx.x;
    const int NIT = Ktot >> 6;
    const int wid = tid >> 5, lane = tid & 31;
    const int gid = lane >> 2, tig = lane & 3;
    const int wm = (wid >> 2) * 64, wn = (wid & 3) * 32;

    float acc[4][4][4];
    #pragma unroll
    for (int i = 0; i < 4; i++)
        #pragma unroll
        for (int j = 0; j < 4; j++)
            #pragma unroll
            for (int k = 0; k < 4; k++) acc[i][j][k] = 0.f;

    auto load_stage = [&](int st, int it) {
        const int k0 = it << 6;
        __half* as = Asm + st*ASZ;
        __half* bs = Bsm + st*BSZ;
        const __half* Ap = A0;
        int kc = k0;
        if (NSEG > 1) {
            int s = k0 >> 10;
            Ap = (s == 0) ? A0 : (s == 1) ? A1 : A2;
            kc = k0 & 1023;
        }
        #pragma unroll
        for (int j = 0; j < 4; j++) {
            int id = tid + j*256;
            if (AL == 0) {
                int r = id >> 3, c = (id & 7) * 8;
                cp_async16(as + r*PA + c, Ap + (size_t)(bm*128 + r)*lda + kc + c);
            } else {
                int r = id >> 4, c = (id & 15) * 8;
                cp_async16(as + r*PA + c, A0 + (size_t)(k0 + r)*lda + bm*128 + c);
            }
        }
        #pragma unroll
        for (int j = 0; j < 4; j++) {
            int id = tid + j*256;
            if (BL == 0) {
                int r = id >> 4, c = (id & 15) * 8;
                cp_async16(bs + r*PB + c, Bz + (size_t)(k0 + r)*ldb + bn*128 + c);
            } else {
                int r = id >> 3, c = (id & 7) * 8;
                cp_async16(bs + r*PB + c, Bz + (size_t)(bn*128 + r)*ldb + k0 + c);
            }
        }
    };

    auto compute_stage = [&](int st) {
        const __half* as = Asm + st*ASZ;
        const __half* bs = Bsm + st*BSZ;
        const int g8 = lane >> 3, i8 = lane & 7;
        #pragma unroll
        for (int ks = 0; ks < 4; ks++) {
            uint32_t af[4][4];
            #pragma unroll
            for (int mt = 0; mt < 4; mt++) {
                if (AL == 0) {
                    uint32_t a = smaddr(as + (wm + mt*16 + (lane & 15))*PA + ks*16 + (lane >> 4)*8);
                    ldsm4(af[mt][0], af[mt][1], af[mt][2], af[mt][3], a);
                } else {
                    uint32_t a = smaddr(as + (ks*16 + (g8 >> 1)*8 + i8)*PA + wm + mt*16 + (g8 & 1)*8);
                    ldsm4t(af[mt][0], af[mt][1], af[mt][2], af[mt][3], a);
                }
            }
            uint32_t bf[4][2];
            #pragma unroll
            for (int p = 0; p < 2; p++) {
                uint32_t q0, q1, q2, q3;
                if (BL == 1) {
                    uint32_t a = smaddr(bs + (wn + p*16 + (g8 >> 1)*8 + i8)*PB + ks*16 + (g8 & 1)*8);
                    ldsm4(q0, q1, q2, q3, a);
                } else {
                    uint32_t a = smaddr(bs + (ks*16 + (g8 & 1)*8 + i8)*PB + wn + p*16 + (g8 >> 1)*8);
                    ldsm4t(q0, q1, q2, q3, a);
                }
                bf[2*p][0] = q0; bf[2*p][1] = q1;
                bf[2*p+1][0] = q2; bf[2*p+1][1] = q3;
            }
            #pragma unroll
            for (int mt = 0; mt < 4; mt++)
                #pragma unroll
                for (int nt = 0; nt < 4; nt++)
                    mma_f16(acc[mt][nt], af[mt], bf[nt]);
        }
    };

    load_stage(0, 0); CP_COMMIT();
    if (NIT > 1) { load_stage(1, 1); CP_COMMIT(); }
    int buf = 0;
    for (int it = 0; it < NIT; ++it) {
        if (it + 1 < NIT) { CP_WAIT(1); } else { CP_WAIT(0); }
        __syncthreads();
        if (it + 2 < NIT) load_stage((buf + 2 >= STG) ? buf + 2 - STG : buf + 2, it + 2);
        CP_COMMIT();
        compute_stage(buf);
        buf = (buf + 1 >= STG) ? buf + 1 - STG : buf + 1;
    }

    /* ---------------- epilogue ---------------- */
    float rsum[4][2], csum[4][2];
    if (EPI == 4) {
        #pragma unroll
        for (int i = 0; i < 4; i++) { rsum[i][0] = rsum[i][1] = 0.f; csum[i][0] = csum[i][1] = 0.f; }
    }

    #pragma unroll
    for (int mt = 0; mt < 4; mt++) {
        #pragma unroll
        for (int nt = 0; nt < 4; nt++) {
            int r0  = bm*128 + wm + mt*16 + gid;
            int col = bn*128 + wn + nt*8 + 2*tig;
            float c0 = acc[mt][nt][0], c1 = acc[mt][nt][1];
            float c2 = acc[mt][nt][2], c3 = acc[mt][nt][3];
            if (EPI == 4) { c0 *= ATTN_SCALE; c1 *= ATTN_SCALE; c2 *= ATTN_SCALE; c3 *= ATTN_SCALE; }
            if (EPI == 3) {
                float2 bv = *(const float2*)(bias + col);
                c0 += bv.x; c1 += bv.y; c2 += bv.x; c3 += bv.y;
            }
            if (EPI == 2 || EPI == 4) {
                __half2 h01 = __floats2half2_rn(c0, c1);
                __half2 h23 = __floats2half2_rn(c2, c3);
                *(__half2*)&Chz[(size_t)r0*ldc + col]     = h01;
                *(__half2*)&Chz[(size_t)(r0+8)*ldc + col] = h23;
                if (EPI == 4) {
                    /* stats on the f16-rounded values (matches downstream mix) */
                    float2 f01 = __half22float2(h01);
                    float2 f23 = __half22float2(h23);
                    float e0 = __expf(f01.x), e1 = __expf(f01.y);
                    float e2 = __expf(f23.x), e3 = __expf(f23.y);
                    rsum[mt][0] += e0 + e1;
                    rsum[mt][1] += e2 + e3;
                    csum[nt][0] += e0 + e2;
                    csum[nt][1] += e1 + e3;
                }
            } else {
                *(float2*)&Cfz[(size_t)r0*ldc + col]     = make_float2(c0, c1);
                *(float2*)&Cfz[(size_t)(r0+8)*ldc + col] = make_float2(c2, c3);
            }
        }
    }

    if (EPI == 4) {
        /* reduce rows over tig (32-col groups), cols over gid (64-row groups) */
        #pragma unroll
        for (int mt = 0; mt < 4; mt++)
            #pragma unroll
            for (int j = 0; j < 2; j++) {
                float v = rsum[mt][j];
                v += __shfl_xor_sync(0xffffffffu, v, 1);
                v += __shfl_xor_sync(0xffffffffu, v, 2);
                rsum[mt][j] = v;
            }
        #pragma unroll
        for (int nt = 0; nt < 4; nt++)
            #pragma unroll
            for (int j = 0; j < 2; j++) {
                float v = csum[nt][j];
                v += __shfl_xor_sync(0xffffffffu, v, 4);
                v += __shfl_xor_sync(0xffffffffu, v, 8);
                v += __shfl_xor_sync(0xffffffffu, v, 16);
                csum[nt][j] = v;
            }
        __syncthreads();                 /* smem stages no longer needed */
        float* sf   = (float*)sm16;
        float* srow = sf;                /* [4][128] */
        float* scol = sf + 512;          /* [2][128] */
        if (tig == 0) {
            #pragma unroll
            for (int mt = 0; mt < 4; mt++) {
                srow[(wid & 3)*128 + wm + mt*16 + gid]     = rsum[mt][0];
                srow[(wid & 3)*128 + wm + mt*16 + gid + 8] = rsum[mt][1];
            }
        }
        if (gid == 0) {
            #pragma unroll
            for (int nt = 0; nt < 4; nt++) {
                scol[(wid >> 2)*128 + wn + nt*8 + 2*tig]     = csum[nt][0];
                scol[(wid >> 2)*128 + wn + nt*8 + 2*tig + 1] = csum[nt][1];
            }
        }
        __syncthreads();
        if (tid < 128) {
            float rp = srow[tid] + srow[128 + tid] + srow[256 + tid] + srow[384 + tid];
            g_rpart[(size_t)bn*ZBN + z*NTOK + bm*128 + tid] = rp;
            float cp = scol[tid] + scol[128 + tid];
            g_cpart[(size_t)bm*ZBN + z*NTOK + bn*128 + tid] = cp;
        }
    }
}

/* ------------------- GEMM wrappers ------------------- */

/* merged cond/refv projections: grid (8, 32, 2) */
__global__ __launch_bounds__(256)
void k_proj()
{
    const int zi = blockIdx.z;
    const __half* A1 = zi ? g_rn16 : g_cn16;
    const __half* B  = zi ? g_Wv16 : g_Wk16;
    __half* out      = zi ? g_refv16 : g_cond16;
    int Ktot         = zi ? 2*DIM : 3*DIM;
    hgemm_body<0,0,3,2>(g_xn16, A1, g_rn16, DIM, B, DIM,
                        nullptr, out, DIM, Ktot, nullptr,
                        0, blockIdx.y, blockIdx.x);
}

/* sim + fused softmax stats: grid (8, 8, ZB) */
__global__ __launch_bounds__(256)
void k_sim()
{
    const int z = blockIdx.z, zb = z >> 3, zh = z & 7;
    const __half* A = g_cond16 + (size_t)zb*NTOK*DIM + zh*DHEAD;
    const __half* B = g_refv16 + (size_t)zb*NTOK*DIM + zh*DHEAD;
    __half* C = g_sim16 + (size_t)z*NTOK*NTOK;
    hgemm_body<0,1,1,4>(A, nullptr, nullptr, DIM, B, DIM,
                        nullptr, C, NTOK, DHEAD, nullptr,
                        z, blockIdx.y, blockIdx.x);
}

/* merged PV + ctx^T GEMMs: grid (1, 8, 64) */
__global__ __launch_bounds__(256)
void k_pvctx(float* __restrict__ out2)
{
    if (blockIdx.z < 32) {
        const int z = blockIdx.z, zb = z >> 3, zh = z & 7;
        hgemm_body<0,0,1,2>(g_attn16 + (size_t)z*NTOK*NTOK, nullptr, nullptr, NTOK,
                            g_refv16 + (size_t)zb*NTOK*DIM + zh*DHEAD, DIM,
                            nullptr, g_outpre16 + (size_t)zb*NTOK*DIM + zh*DHEAD, DIM,
                            NTOK, nullptr, z, blockIdx.y, blockIdx.x);
    } else {
        const int z = blockIdx.z - 32, zb = z >> 3, zh = z & 7;
        hgemm_body<1,0,1,0>(g_ctx16 + (size_t)z*NTOK*NTOK, nullptr, nullptr, NTOK,
                            g_cond16 + (size_t)zb*NTOK*DIM + zh*DHEAD, DIM,
                            out2 + (size_t)zb*NTOK*DIM + zh*DHEAD, nullptr, DIM,
                            NTOK, nullptr, z, blockIdx.y, blockIdx.x);
    }
}

/* Wo projection: grid (8, 32, 1) */
__global__ __launch_bounds__(256)
void k_wo(float* __restrict__ out1, const float* __restrict__ bo)
{
    hgemm_body<0,0,1,3>(g_outpre16, nullptr, nullptr, DIM, g_Wo16, DIM,
                        out1, nullptr, DIM, DIM, bo,
                        0, blockIdx.y, blockIdx.x);
}

/* ------------------- f32 -> f16 convert ------------------- */
__global__ __launch_bounds__(256)
void k_f2h(const float* __restrict__ s, __half* __restrict__ d, int n)
{
    int i = (blockIdx.x * 256 + threadIdx.x) * 4;
    if (i < n) {
        float4 v = *(const float4*)(s + i);
        *(__half2*)(d + i)     = __floats2half2_rn(v.x, v.y);
        *(__half2*)(d + i + 2) = __floats2half2_rn(v.z, v.w);
    }
}

/* ------------------- LayerNorm -> f16 ------------------- */
__global__ __launch_bounds__(256)
void k_layernorm(const float* __restrict__ x, const float* __restrict__ ci,
                 const float* __restrict__ ref,
                 const float* __restrict__ lw, const float* __restrict__ lb,
                 const float* __restrict__ cw, const float* __restrict__ cb)
{
    int row = blockIdx.x;
    int which = blockIdx.y;
    const float* src = (which == 0) ? x : (which == 1) ? ref : ci;
    const float* w   = (which == 2) ? cw : lw;
    const float* bb  = (which == 2) ? cb : lb;
    __half* dst      = (which == 0) ? g_xn16 : (which == 1) ? g_rn16 : g_cn16;

    const float* p = src + (size_t)row * DIM;
    int t = threadIdx.x;
    float4 v = *(const float4*)(p + t * 4);
    float s  = v.x + v.y + v.z + v.w;
    float s2 = v.x*v.x + v.y*v.y + v.z*v.z + v.w*v.w;
    for (int o = 16; o; o >>= 1) {
        s  += __shfl_xor_sync(0xffffffffu, s,  o);
        s2 += __shfl_xor_sync(0xffffffffu, s2, o);
    }
    __shared__ float rs1[8], rs2[8];
    if ((t & 31) == 0) { rs1[t >> 5] = s; rs2[t >> 5] = s2; }
    __syncthreads();
    float S = 0.f, S2 = 0.f;
    #pragma unroll
    for (int i = 0; i < 8; i++) { S += rs1[i]; S2 += rs2[i]; }
    float mu  = S * (1.0f / DIM);
    float var = S2 * (1.0f / DIM) - mu * mu;
    float rstd = rsqrtf(var + LN_EPS);
    int c = t * 4;
    float4 wv = *(const float4*)(w + c);
    float4 bv = *(const float4*)(bb + c);
    float o0 = (v.x - mu) * rstd * wv.x + bv.x;
    float o1 = (v.y - mu) * rstd * wv.y + bv.y;
    float o2 = (v.z - mu) * rstd * wv.z + bv.z;
    float o3 = (v.w - mu) * rstd * wv.w + bv.w;
    __half* dp = dst + (size_t)row * DIM + c;
    *(__half2*)(dp)     = __floats2half2_rn(o0, o1);
    *(__half2*)(dp + 2) = __floats2half2_rn(o2, o3);
}

/* ------------------- stats partial reduce -> rinv/cinv ------------------- */
__global__ __launch_bounds__(256)
void k_redrc()
{
    int idx = blockIdx.x * 256 + threadIdx.x;
    float r = 0.f, c = 0.f;
    #pragma unroll
    for (int p = 0; p < 8; p++) {
        r += g_rpart[(size_t)p * ZBN + idx];
        c += g_cpart[(size_t)p * ZBN + idx];
    }
    g_rinv[idx] = 1.0f / r;
    g_cinv[idx] = 1.0f / c;
}

/* ------------------- softmax + talking-heads mix ------------------- */
__global__ __launch_bounds__(256)
void k_mix(const float* __restrict__ thw, const float* __restrict__ cthw)
{
    __shared__ float sth[64], scth[64];
    if (threadIdx.x < 64) sth[threadIdx.x] = thw[threadIdx.x];
    else if (threadIdx.x < 128) scth[threadIdx.x - 64] = cthw[threadIdx.x - 64];
    __syncthreads();

    size_t idx = (size_t)blockIdx.x * blockDim.x + threadIdx.x;
    int j4 = (int)(idx & 255);
    int i  = (int)((idx >> 8) & 1023);
    int b  = (int)(idx >> 18);

    float4 pr[NHEAD], pc[NHEAD];
    #pragma unroll
    for (int h = 0; h < NHEAD; h++) {
        int zh = b * NHEAD + h;
        size_t off = ((size_t)zh * NTOK + i) * NTOK + j4 * 4;
        float2 raw = *(const float2*)(g_sim16 + off);
        float2 f0 = __half22float2(*(__half2*)&raw.x);
        float2 f1 = __half22float2(*(__half2*)&raw.y);
        float e0 = __expf(f0.x), e1 = __expf(f0.y);
        float e2 = __expf(f1.x), e3 = __expf(f1.y);
        float ri = g_rinv[zh * NTOK + i];
        pr[h] = make_float4(e0 * ri, e1 * ri, e2 * ri, e3 * ri);
        float4 cv = *(const float4*)(g_cinv + zh * NTOK + j4 * 4);
        pc[h] = make_float4(e0 * cv.x, e1 * cv.y, e2 * cv.z, e3 * cv.w);
    }
    #pragma unroll
    for (int g = 0; g < NHEAD; g++) {
        float4 a = make_float4(0.f, 0.f, 0.f, 0.f);
        float4 c = make_float4(0.f, 0.f, 0.f, 0.f);
        #pragma unroll
        for (int h = 0; h < NHEAD; h++) {
            float wa = sth[g * 8 + h], wc = scth[g * 8 + h];
            a.x += wa * pr[h].x; a.y += wa * pr[h].y;
            a.z += wa * pr[h].z; a.w += wa * pr[h].w;
            c.x += wc * pc[h].x; c.y += wc * pc[h].y;
            c.z += wc * pc[h].z; c.w += wc * pc[h].w;
        }
        size_t off = ((size_t)(b * NHEAD + g) * NTOK + i) * NTOK + j4 * 4;
        *(__half2*)(g_attn16 + off)     = __floats2half2_rn(a.x, a.y);
        *(__half2*)(g_attn16 + off + 2) = __floats2half2_rn(a.z, a.w);
        *(__half2*)(g_ctx16 + off)      = __floats2half2_rn(c.x, c.y);
        *(__half2*)(g_ctx16 + off + 2)  = __floats2half2_rn(c.z, c.w);
    }
}

/* ------------------- launch ------------------- */
extern "C" void kernel_launch(void* const* d_in, const int* in_sizes, int n_in,
                              void* d_out, int out_size)
{
    const float* x    = (const float*)d_in[0];
    const float* ci   = (const float*)d_in[1];
    const float* ref  = (const float*)d_in[2];
    const float* lnw  = (const float*)d_in[3];
    const float* lnb  = (const float*)d_in[4];
    const float* clw  = (const float*)d_in[5];
    const float* clb  = (const float*)d_in[6];
    const float* Wk   = (const float*)d_in[7];
    const float* Wv   = (const float*)d_in[8];
    const float* Wo   = (const float*)d_in[9];
    const float* bo   = (const float*)d_in[10];
    const float* thw  = (const float*)d_in[11];
    const float* cthw = (const float*)d_in[12];

    float* out1 = (float*)d_out;
    float* out2 = (float*)d_out + (size_t)ROWS * DIM;

    __half *wk16, *wv16, *wo16;
    cudaGetSymbolAddress((void**)&wk16, g_Wk16);
    cudaGetSymbolAddress((void**)&wv16, g_Wv16);
    cudaGetSymbolAddress((void**)&wo16, g_Wo16);

    /* dynamic smem (bytes): 3 stages, BK=64 */
    const int SM_MK_KN = 3 * (128*72 + 64*136) * 2;  /* 107520 */
    const int SM_MK_NK = 3 * (128*72 + 128*72) * 2;  /* 110592 */

    cudaFuncSetAttribute((const void*)k_proj,  cudaFuncAttributeMaxDynamicSharedMemorySize, SM_MK_KN);
    cudaFuncSetAttribute((const void*)k_sim,   cudaFuncAttributeMaxDynamicSharedMemorySize, SM_MK_NK);
    cudaFuncSetAttribute((const void*)k_pvctx, cudaFuncAttributeMaxDynamicSharedMemorySize, SM_MK_KN);
    cudaFuncSetAttribute((const void*)k_wo,    cudaFuncAttributeMaxDynamicSharedMemorySize, SM_MK_KN);

    /* 0. weights -> f16 */
    k_f2h<<<(3*DIM*DIM)/1024, 256>>>(Wk, wk16, 3*DIM*DIM);
    k_f2h<<<(2*DIM*DIM)/1024, 256>>>(Wv, wv16, 2*DIM*DIM);
    k_f2h<<<(DIM*DIM)/1024, 256>>>(Wo, wo16, DIM*DIM);

    /* 1. LayerNorms -> f16 */
    k_layernorm<<<dim3(ROWS, 3), 256>>>(x, ci, ref, lnw, lnb, clw, clb);

    /* 2+3. merged cond & refv projections */
    k_proj<<<dim3(DIM/128, ROWS/128, 2), 256, SM_MK_KN>>>();

    /* 4. sim (+fused softmax stats partials) */
    k_sim<<<dim3(NTOK/128, NTOK/128, ZB), 256, SM_MK_NK>>>();

    /* 5. reduce partials -> rinv, cinv */
    k_redrc<<<ZBN/256, 256>>>();

    /* 6. softmax + talking-heads -> f16 attn/ctx */
    k_mix<<<(BATCH * NTOK * (NTOK / 4)) / 256, 256>>>(thw, cthw);

    /* 7+8. merged PV and ctx^T GEMMs */
    k_pvctx<<<dim3(DHEAD/128, NTOK/128, 2*ZB), 256, SM_MK_KN>>>(out2);

    /* 9. out1 = outpre @ Wo + bo */
    k_wo<<<dim3(DIM/128, ROWS/128, 1), 256, SM_MK_KN>>>(out1, bo);
}